// round 1
// baseline (speedup 1.0000x reference)
#include <cuda_runtime.h>

// ---------------------------------------------------------------------------
// MultiHeadAttention WITHOUT softmax:
//   x = (mask(QK^T / sqrt(dk))) V     ==>   x = Q (K^T V)/sqrt(dk)  + mask fix
// Shapes: B=2, S=2048, D=768, H=12, dk=64.  All fp32.
// ---------------------------------------------------------------------------

#define D_MODEL 768
#define SEQ     2048
#define BATCH   2
#define NTOK    (BATCH*SEQ)          // 4096
#define NHEAD   12
#define DK      64
#define BHTOT   (BATCH*NHEAD)        // 24
#define NCHUNK  16
#define CHUNK_T (SEQ/NCHUNK)         // 128
#define SCALE   0.125f               // 1/sqrt(64)
#define NEGV    (-1000000000.0f)

// Scratch (allocation-free: __device__ globals)
__device__ float g_Qp[NTOK*D_MODEL];
__device__ float g_Kp[NTOK*D_MODEL];
__device__ float g_Vp[NTOK*D_MODEL];
__device__ float g_X [NTOK*D_MODEL];
__device__ float g_Mpart[BHTOT*NCHUNK*DK*DK];
__device__ float g_M[BHTOT*DK*DK];

// ---------------------------------------------------------------------------
// GEMM: C[NTOK? rows, 768] = A[rows,768] @ W[768,768] + bias
// 64x64 block tile, BK=16, 256 threads, 4x4 micro-tile per thread.
// ---------------------------------------------------------------------------
__global__ __launch_bounds__(256) void gemm_bias_768(
    const float* __restrict__ A,
    const float* __restrict__ W,
    const float* __restrict__ bias,
    float* __restrict__ C)
{
    __shared__ float As[16][65];   // [k][row], padded to kill store conflicts
    __shared__ float Ws[16][64];   // [k][col]

    const int tid = threadIdx.x;
    const int tx  = tid & 15;      // 16 col groups
    const int ty  = tid >> 4;      // 16 row groups
    const int rowBase = blockIdx.y * 64;
    const int colBase = blockIdx.x * 64;

    // A-tile load mapping: each thread loads float4 along k
    const int aIdx = tid * 4;
    const int ar   = aIdx >> 4;    // 0..63 row in tile
    const int ak   = aIdx & 15;    // 0,4,8,12
    // W-tile load mapping
    const int wIdx = tid * 4;
    const int wk   = wIdx >> 6;    // 0..15
    const int wc   = wIdx & 63;    // multiple of 4

    float acc[4][4];
    #pragma unroll
    for (int i = 0; i < 4; i++)
        #pragma unroll
        for (int j = 0; j < 4; j++) acc[i][j] = 0.0f;

    for (int k0 = 0; k0 < D_MODEL; k0 += 16) {
        const float4 av = *(const float4*)(A + (size_t)(rowBase + ar) * D_MODEL + k0 + ak);
        const float4 wv = *(const float4*)(W + (size_t)(k0 + wk) * D_MODEL + colBase + wc);
        __syncthreads();
        As[ak + 0][ar] = av.x;
        As[ak + 1][ar] = av.y;
        As[ak + 2][ar] = av.z;
        As[ak + 3][ar] = av.w;
        *(float4*)&Ws[wk][wc] = wv;
        __syncthreads();

        #pragma unroll
        for (int kk = 0; kk < 16; kk++) {
            const float4 b4 = *(const float4*)&Ws[kk][tx * 4];
            const float a0 = As[kk][ty * 4 + 0];
            const float a1 = As[kk][ty * 4 + 1];
            const float a2 = As[kk][ty * 4 + 2];
            const float a3 = As[kk][ty * 4 + 3];
            acc[0][0] += a0 * b4.x; acc[0][1] += a0 * b4.y; acc[0][2] += a0 * b4.z; acc[0][3] += a0 * b4.w;
            acc[1][0] += a1 * b4.x; acc[1][1] += a1 * b4.y; acc[1][2] += a1 * b4.z; acc[1][3] += a1 * b4.w;
            acc[2][0] += a2 * b4.x; acc[2][1] += a2 * b4.y; acc[2][2] += a2 * b4.z; acc[2][3] += a2 * b4.w;
            acc[3][0] += a3 * b4.x; acc[3][1] += a3 * b4.y; acc[3][2] += a3 * b4.z; acc[3][3] += a3 * b4.w;
        }
    }

    #pragma unroll
    for (int i = 0; i < 4; i++) {
        const int r = rowBase + ty * 4 + i;
        #pragma unroll
        for (int j = 0; j < 4; j++) {
            const int c = colBase + tx * 4 + j;
            C[(size_t)r * D_MODEL + c] = acc[i][j] + bias[c];
        }
    }
}

// ---------------------------------------------------------------------------
// Per (b,h): partial M = K^T V over a t-chunk of 128 rows. Grid (16,24).
// ---------------------------------------------------------------------------
__global__ __launch_bounds__(256) void kv_partial_kernel()
{
    const int chunk = blockIdx.x;          // 0..15
    const int bh    = blockIdx.y;          // 0..23
    const int b = bh / NHEAD, h = bh % NHEAD;
    const int tid = threadIdx.x;
    const int tx = tid & 15, ty = tid >> 4;

    __shared__ float ks[8][64];
    __shared__ float vs[8][64];

    const int rowBase = b * SEQ + chunk * CHUNK_T;
    const int colOff  = h * DK;

    const int li = tid * 2;
    const int lr = li >> 6;    // 0..7
    const int lc = li & 63;    // even

    float acc[4][4];
    #pragma unroll
    for (int i = 0; i < 4; i++)
        #pragma unroll
        for (int j = 0; j < 4; j++) acc[i][j] = 0.0f;

    for (int tt = 0; tt < CHUNK_T; tt += 8) {
        const size_t off = (size_t)(rowBase + tt + lr) * D_MODEL + colOff + lc;
        const float2 k2 = *(const float2*)(g_Kp + off);
        const float2 v2 = *(const float2*)(g_Vp + off);
        __syncthreads();
        ks[lr][lc] = k2.x; ks[lr][lc + 1] = k2.y;
        vs[lr][lc] = v2.x; vs[lr][lc + 1] = v2.y;
        __syncthreads();

        #pragma unroll
        for (int r = 0; r < 8; r++) {
            const float a0 = ks[r][ty * 4 + 0];
            const float a1 = ks[r][ty * 4 + 1];
            const float a2 = ks[r][ty * 4 + 2];
            const float a3 = ks[r][ty * 4 + 3];
            const float b0 = vs[r][tx * 4 + 0];
            const float b1 = vs[r][tx * 4 + 1];
            const float b2 = vs[r][tx * 4 + 2];
            const float b3 = vs[r][tx * 4 + 3];
            acc[0][0] += a0 * b0; acc[0][1] += a0 * b1; acc[0][2] += a0 * b2; acc[0][3] += a0 * b3;
            acc[1][0] += a1 * b0; acc[1][1] += a1 * b1; acc[1][2] += a1 * b2; acc[1][3] += a1 * b3;
            acc[2][0] += a2 * b0; acc[2][1] += a2 * b1; acc[2][2] += a2 * b2; acc[2][3] += a2 * b3;
            acc[3][0] += a3 * b0; acc[3][1] += a3 * b1; acc[3][2] += a3 * b2; acc[3][3] += a3 * b3;
        }
    }

    float* mp = g_Mpart + ((size_t)bh * NCHUNK + chunk) * DK * DK;
    #pragma unroll
    for (int i = 0; i < 4; i++)
        #pragma unroll
        for (int j = 0; j < 4; j++)
            mp[(ty * 4 + i) * DK + tx * 4 + j] = acc[i][j];
}

// Reduce 16 partials -> M, fold in 1/sqrt(dk)
__global__ __launch_bounds__(256) void kv_reduce_kernel()
{
    const int bh = blockIdx.x;
    for (int e = threadIdx.x; e < DK * DK; e += 256) {
        float s = 0.0f;
        #pragma unroll
        for (int c = 0; c < NCHUNK; c++)
            s += g_Mpart[((size_t)bh * NCHUNK + c) * DK * DK + e];
        g_M[(size_t)bh * DK * DK + e] = s * SCALE;
    }
}

// ---------------------------------------------------------------------------
// X[n, h*64+j] = sum_i Qp[n, h*64+i] * M[bh][i][j].  Grid (128 row-tiles, 12).
// ---------------------------------------------------------------------------
__global__ __launch_bounds__(256) void qm_kernel()
{
    const int h  = blockIdx.y;
    const int n0 = blockIdx.x * 32;
    const int b  = n0 / SEQ;               // 32 divides 2048: no straddle
    const int bh = b * NHEAD + h;
    const int tid = threadIdx.x;

    __shared__ float Ms[DK * DK];          // 16 KB
    __shared__ float Qs[32 * DK];          // 8 KB

    const float4* msrc = (const float4*)(g_M + (size_t)bh * DK * DK);
    float4* mdst = (float4*)Ms;
    #pragma unroll
    for (int i = tid; i < 1024; i += 256) mdst[i] = msrc[i];

    for (int i = tid; i < 512; i += 256) {
        const int r = i >> 4;
        const int c = (i & 15) * 4;
        *(float4*)&Qs[r * 64 + c] =
            *(const float4*)(g_Qp + (size_t)(n0 + r) * D_MODEL + h * DK + c);
    }
    __syncthreads();

    const int r  = tid >> 3;
    const int j0 = (tid & 7) * 8;
    float acc[8];
    #pragma unroll
    for (int j = 0; j < 8; j++) acc[j] = 0.0f;

    #pragma unroll 8
    for (int i = 0; i < 64; i++) {
        const float qv = Qs[r * 64 + i];
        #pragma unroll
        for (int j = 0; j < 8; j++) acc[j] += qv * Ms[i * 64 + j0 + j];
    }

    float* xr = g_X + (size_t)(n0 + r) * D_MODEL + h * DK + j0;
    #pragma unroll
    for (int j = 0; j < 8; j++) xr[j] = acc[j];
}

// ---------------------------------------------------------------------------
// Exact mask handling: for every mask[s,t]==0 add (NEG - q.k/8) * v[t] to x.
// All-ones mask => pure 16 MB scan, no corrections.
// ---------------------------------------------------------------------------
__global__ __launch_bounds__(256) void mask_correction_kernel(const int* __restrict__ mask)
{
    const int s = blockIdx.x;
    const int* mrow = mask + (size_t)s * SEQ;
    for (int t = threadIdx.x; t < SEQ; t += 256) {
        if (mrow[t] == 0) {
            for (int b = 0; b < BATCH; b++) {
                const float* qrow = g_Qp + (size_t)(b * SEQ + s) * D_MODEL;
                const float* krow = g_Kp + (size_t)(b * SEQ + t) * D_MODEL;
                const float* vrow = g_Vp + (size_t)(b * SEQ + t) * D_MODEL;
                float* xrow = g_X + (size_t)(b * SEQ + s) * D_MODEL;
                for (int h = 0; h < NHEAD; h++) {
                    float raw = 0.0f;
                    #pragma unroll 8
                    for (int i = 0; i < DK; i++)
                        raw += qrow[h * DK + i] * krow[h * DK + i];
                    const float delta = NEGV - raw * SCALE;
                    for (int j = 0; j < DK; j++)
                        atomicAdd(&xrow[h * DK + j], delta * vrow[h * DK + j]);
                }
            }
        }
    }
}

// ---------------------------------------------------------------------------
extern "C" void kernel_launch(void* const* d_in, const int* in_sizes, int n_in,
                              void* d_out, int out_size)
{
    const float* q    = (const float*)d_in[0];
    const float* k    = (const float*)d_in[1];
    const float* v    = (const float*)d_in[2];
    const int*   mask = (const int*)  d_in[3];
    const float* w_q  = (const float*)d_in[4];
    const float* b_q  = (const float*)d_in[5];
    const float* w_k  = (const float*)d_in[6];
    const float* b_k  = (const float*)d_in[7];
    const float* w_v  = (const float*)d_in[8];
    const float* b_v  = (const float*)d_in[9];
    const float* w_o  = (const float*)d_in[10];
    const float* b_o  = (const float*)d_in[11];
    float* out = (float*)d_out;

    float *Qp = nullptr, *Kp = nullptr, *Vp = nullptr, *X = nullptr;
    cudaGetSymbolAddress((void**)&Qp, g_Qp);
    cudaGetSymbolAddress((void**)&Kp, g_Kp);
    cudaGetSymbolAddress((void**)&Vp, g_Vp);
    cudaGetSymbolAddress((void**)&X,  g_X);

    const dim3 gg(D_MODEL / 64, NTOK / 64);   // (12, 64)

    gemm_bias_768<<<gg, 256>>>(q, w_q, b_q, Qp);
    gemm_bias_768<<<gg, 256>>>(k, w_k, b_k, Kp);
    gemm_bias_768<<<gg, 256>>>(v, w_v, b_v, Vp);

    kv_partial_kernel<<<dim3(NCHUNK, BHTOT), 256>>>();
    kv_reduce_kernel<<<BHTOT, 256>>>();
    qm_kernel<<<dim3(NTOK / 32, NHEAD), 256>>>();
    mask_correction_kernel<<<SEQ, 256>>>(mask);

    gemm_bias_768<<<gg, 256>>>(X, w_o, b_o, out);
}

// round 4
// speedup vs baseline: 2.3579x; 2.3579x over previous
#include <cuda_runtime.h>
#include <cuda_bf16.h>
#include <cstdint>

// ---------------------------------------------------------------------------
// MHA without softmax:  x = Q (K^T V)/sqrt(dk) (+ exact mask correction)
// Projections: bf16 hi/lo split (K=2304) on classic mma.sync HMMA,
// fp32 accumulate. B=2, S=2048, D=768, H=12, dk=64.
// ---------------------------------------------------------------------------

#define D_MODEL 768
#define SEQ     2048
#define BATCH   2
#define NTOK    (BATCH*SEQ)          // 4096
#define NHEAD   12
#define DK      64
#define BHTOT   (BATCH*NHEAD)        // 24
#define NCHUNK  16
#define CHUNK_T (SEQ/NCHUNK)         // 128
#define SCALE   0.125f
#define NEGV    (-1000000000.0f)

#define GK      2304                 // 3 * 768 (hi | hi | lo split K)
#define BK      32                   // bf16 per pipeline stage
#define NKSTEP  (GK/BK)              // 72
#define STAGES  3
#define SM_ABYTES 8192               // 128 rows * 64B
#define SM_BBYTES 4096               // 64 rows * 64B
#define STAGE_BYTES (SM_ABYTES + SM_BBYTES)

// Scratch (allocation-free)
__device__ float g_Qp[NTOK*D_MODEL];
__device__ float g_Kp[NTOK*D_MODEL];
__device__ float g_Vp[NTOK*D_MODEL];
__device__ float g_X [NTOK*D_MODEL];
__device__ float g_Mpart[BHTOT*NCHUNK*DK*DK];
__device__ float g_M[BHTOT*DK*DK];
__device__ __nv_bfloat16 g_Aext[(size_t)NTOK*GK];
__device__ __nv_bfloat16 g_Wext[(size_t)D_MODEL*GK];

// ---------------------------------------------------------------------------
// PTX helpers (generic sm_80+ ISA only — compiles for compute_103)
// ---------------------------------------------------------------------------
__device__ __forceinline__ uint32_t smem_u32(const void* p) {
    uint32_t a;
    asm("{ .reg .u64 t; cvta.to.shared.u64 t, %1; cvt.u32.u64 %0, t; }" : "=r"(a) : "l"(p));
    return a;
}
__device__ __forceinline__ void cp16(uint32_t saddr, const void* g) {
    asm volatile("cp.async.cg.shared.global [%0], [%1], 16;" :: "r"(saddr), "l"(g));
}
#define CP_COMMIT() asm volatile("cp.async.commit_group;" ::: "memory")
#define CP_WAIT1()  asm volatile("cp.async.wait_group 1;" ::: "memory")

__device__ __forceinline__ void ldsm4(uint32_t* r, uint32_t addr) {
    asm volatile("ldmatrix.sync.aligned.m8n8.x4.shared.b16 {%0,%1,%2,%3}, [%4];"
                 : "=r"(r[0]), "=r"(r[1]), "=r"(r[2]), "=r"(r[3]) : "r"(addr));
}
__device__ __forceinline__ void mma16816(float* c, const uint32_t* a,
                                         uint32_t b0, uint32_t b1) {
    asm volatile(
        "mma.sync.aligned.m16n8k16.row.col.f32.bf16.bf16.f32 "
        "{%0,%1,%2,%3}, {%4,%5,%6,%7}, {%8,%9}, {%0,%1,%2,%3};"
        : "+f"(c[0]), "+f"(c[1]), "+f"(c[2]), "+f"(c[3])
        : "r"(a[0]), "r"(a[1]), "r"(a[2]), "r"(a[3]), "r"(b0), "r"(b1));
}
// 16B-chunk swizzle for 64B rows: conflict-free for cp.async stores + ldmatrix
__device__ __forceinline__ uint32_t swz(int r, int c) {
    return (uint32_t)(r * 64 + ((c ^ ((r >> 1) & 3)) << 4));
}

// ---------------------------------------------------------------------------
// Conversion: fp32 activations [rows,768] -> bf16 ext [rows,2304] = [hi|hi|lo]
// ---------------------------------------------------------------------------
__global__ __launch_bounds__(256) void convert_act(
    const float* __restrict__ in, __nv_bfloat16* __restrict__ out, int total)
{
    int idx = blockIdx.x * 256 + threadIdx.x;
    if (idx >= total) return;
    int r = idx / D_MODEL, c = idx - r * D_MODEL;
    float a = in[idx];
    __nv_bfloat16 hi = __float2bfloat16_rn(a);
    __nv_bfloat16 lo = __float2bfloat16_rn(a - __bfloat162float(hi));
    size_t ro = (size_t)r * GK;
    out[ro + c]        = hi;
    out[ro + 768 + c]  = hi;
    out[ro + 1536 + c] = lo;
}

// W [768k,768n] (k-major rows) -> Wext [768 n-rows, 2304 k-cols] = [hi ; lo ; hi]
__global__ __launch_bounds__(256) void convert_w(
    const float* __restrict__ W, __nv_bfloat16* __restrict__ out)
{
    __shared__ float t[32][33];
    const int k0 = blockIdx.x * 32, n0 = blockIdx.y * 32;
    const int tx = threadIdx.x & 31, ty = threadIdx.x >> 5;
    #pragma unroll
    for (int i = 0; i < 32; i += 8)
        t[ty + i][tx] = W[(size_t)(k0 + ty + i) * D_MODEL + n0 + tx];
    __syncthreads();
    #pragma unroll
    for (int i = 0; i < 32; i += 8) {
        const int n = n0 + ty + i, k = k0 + tx;
        const float w = t[tx][ty + i];            // = W[k][n]
        __nv_bfloat16 hi = __float2bfloat16_rn(w);
        __nv_bfloat16 lo = __float2bfloat16_rn(w - __bfloat162float(hi));
        size_t ro = (size_t)n * GK;
        out[ro + k]        = hi;
        out[ro + 768 + k]  = lo;
        out[ro + 1536 + k] = hi;
    }
}

// ---------------------------------------------------------------------------
// HMMA GEMM: C[4096,768] = Aext[4096,2304] @ Wext[768,2304]^T + bias
// 128x64 CTA tile, 256 threads (8 warps, 4x2), 32x32 warp tile,
// 3-stage cp.async pipeline, BK=32.
// ---------------------------------------------------------------------------
__global__ __launch_bounds__(256, 2) void gemm_hmma(
    const __nv_bfloat16* __restrict__ A,
    const __nv_bfloat16* __restrict__ B,
    const float* __restrict__ bias,
    float* __restrict__ C)
{
    __shared__ __align__(1024) char smem[STAGES * STAGE_BYTES];
    const int tid  = threadIdx.x;
    const int lane = tid & 31, wid = tid >> 5;
    const int wm = wid & 3, wn = wid >> 2;
    const int rowBase = blockIdx.y * 128;
    const int colBase = blockIdx.x * 64;
    const uint32_t sbase = smem_u32(smem);

    const __nv_bfloat16* Ag = A + (size_t)rowBase * GK;
    const __nv_bfloat16* Bg = B + (size_t)colBase * GK;

    const int lr = tid >> 2;      // load row (A: lr and lr+64; B: lr)
    const int ac = tid & 3;       // 16B chunk within 64B row

    float acc[2][4][4];
    #pragma unroll
    for (int mi = 0; mi < 2; mi++)
        #pragma unroll
        for (int j = 0; j < 4; j++)
            #pragma unroll
            for (int e = 0; e < 4; e++) acc[mi][j][e] = 0.0f;

    // ---- prologue: stages 0,1
    #pragma unroll
    for (int s = 0; s < STAGES - 1; s++) {
        const int ko = s * BK;
        const uint32_t sa = sbase + s * STAGE_BYTES;
        const uint32_t sb = sa + SM_ABYTES;
        cp16(sa + swz(lr, ac),      Ag + (size_t)lr * GK + ko + ac * 8);
        cp16(sa + swz(lr + 64, ac), Ag + (size_t)(lr + 64) * GK + ko + ac * 8);
        cp16(sb + swz(lr, ac),      Bg + (size_t)lr * GK + ko + ac * 8);
        CP_COMMIT();
    }

    const int flr = lane & 15;    // ldmatrix row within 16
    const int flc = lane >> 4;    // ldmatrix 8-bf16 chunk select

    for (int ks = 0; ks < NKSTEP; ks++) {
        CP_WAIT1();
        __syncthreads();

        // issue loads for stage ks+2 (overwrites stage finished at ks-1)
        if (ks + STAGES - 1 < NKSTEP) {
            const int s  = (ks + STAGES - 1) % STAGES;
            const int ko = (ks + STAGES - 1) * BK;
            const uint32_t sa = sbase + s * STAGE_BYTES;
            const uint32_t sb = sa + SM_ABYTES;
            cp16(sa + swz(lr, ac),      Ag + (size_t)lr * GK + ko + ac * 8);
            cp16(sa + swz(lr + 64, ac), Ag + (size_t)(lr + 64) * GK + ko + ac * 8);
            cp16(sb + swz(lr, ac),      Bg + (size_t)lr * GK + ko + ac * 8);
            CP_COMMIT();
        }

        // compute current stage
        const uint32_t sa = sbase + (ks % STAGES) * STAGE_BYTES;
        const uint32_t sb = sa + SM_ABYTES;
        #pragma unroll
        for (int kh = 0; kh < 2; kh++) {
            uint32_t afr[2][4], bfr[2][4];
            const int cc = kh * 2 + flc;
            #pragma unroll
            for (int mi = 0; mi < 2; mi++) {
                const int r = wm * 32 + mi * 16 + flr;
                ldsm4(afr[mi], sa + swz(r, cc));
            }
            #pragma unroll
            for (int ni = 0; ni < 2; ni++) {
                const int r = wn * 32 + ni * 16 + flr;
                ldsm4(bfr[ni], sb + swz(r, cc));
            }
            #pragma unroll
            for (int mi = 0; mi < 2; mi++)
                #pragma unroll
                for (int ni = 0; ni < 2; ni++)
                    #pragma unroll
                    for (int nn = 0; nn < 2; nn++)
                        mma16816(acc[mi][ni * 2 + nn], afr[mi],
                                 bfr[ni][nn], bfr[ni][nn + 2]);
        }
    }

    // ---- epilogue: +bias, write fp32
    #pragma unroll
    for (int mi = 0; mi < 2; mi++) {
        const int row0 = rowBase + wm * 32 + mi * 16 + (lane >> 2);
        #pragma unroll
        for (int j = 0; j < 4; j++) {
            const int col = colBase + wn * 32 + j * 8 + (lane & 3) * 2;
            const float2 bv = *(const float2*)(bias + col);
            float2 o0, o1;
            o0.x = acc[mi][j][0] + bv.x; o0.y = acc[mi][j][1] + bv.y;
            o1.x = acc[mi][j][2] + bv.x; o1.y = acc[mi][j][3] + bv.y;
            *(float2*)(C + (size_t)row0 * D_MODEL + col) = o0;
            *(float2*)(C + (size_t)(row0 + 8) * D_MODEL + col) = o1;
        }
    }
}

// ---------------------------------------------------------------------------
// Attention core (unchanged from round 1 — verified correct)
// ---------------------------------------------------------------------------
__global__ __launch_bounds__(256) void kv_partial_kernel()
{
    const int chunk = blockIdx.x;
    const int bh    = blockIdx.y;
    const int b = bh / NHEAD, h = bh % NHEAD;
    const int tid = threadIdx.x;
    const int tx = tid & 15, ty = tid >> 4;

    __shared__ float ks[8][64];
    __shared__ float vs[8][64];

    const int rowBase = b * SEQ + chunk * CHUNK_T;
    const int colOff  = h * DK;

    const int li = tid * 2;
    const int lr = li >> 6;
    const int lc = li & 63;

    float acc[4][4];
    #pragma unroll
    for (int i = 0; i < 4; i++)
        #pragma unroll
        for (int j = 0; j < 4; j++) acc[i][j] = 0.0f;

    for (int tt = 0; tt < CHUNK_T; tt += 8) {
        const size_t off = (size_t)(rowBase + tt + lr) * D_MODEL + colOff + lc;
        const float2 k2 = *(const float2*)(g_Kp + off);
        const float2 v2 = *(const float2*)(g_Vp + off);
        __syncthreads();
        ks[lr][lc] = k2.x; ks[lr][lc + 1] = k2.y;
        vs[lr][lc] = v2.x; vs[lr][lc + 1] = v2.y;
        __syncthreads();

        #pragma unroll
        for (int r = 0; r < 8; r++) {
            const float a0 = ks[r][ty * 4 + 0];
            const float a1 = ks[r][ty * 4 + 1];
            const float a2 = ks[r][ty * 4 + 2];
            const float a3 = ks[r][ty * 4 + 3];
            const float b0 = vs[r][tx * 4 + 0];
            const float b1 = vs[r][tx * 4 + 1];
            const float b2 = vs[r][tx * 4 + 2];
            const float b3 = vs[r][tx * 4 + 3];
            acc[0][0] += a0 * b0; acc[0][1] += a0 * b1; acc[0][2] += a0 * b2; acc[0][3] += a0 * b3;
            acc[1][0] += a1 * b0; acc[1][1] += a1 * b1; acc[1][2] += a1 * b2; acc[1][3] += a1 * b3;
            acc[2][0] += a2 * b0; acc[2][1] += a2 * b1; acc[2][2] += a2 * b2; acc[2][3] += a2 * b3;
            acc[3][0] += a3 * b0; acc[3][1] += a3 * b1; acc[3][2] += a3 * b2; acc[3][3] += a3 * b3;
        }
    }

    float* mp = g_Mpart + ((size_t)bh * NCHUNK + chunk) * DK * DK;
    #pragma unroll
    for (int i = 0; i < 4; i++)
        #pragma unroll
        for (int j = 0; j < 4; j++)
            mp[(ty * 4 + i) * DK + tx * 4 + j] = acc[i][j];
}

__global__ __launch_bounds__(256) void kv_reduce_kernel()
{
    const int bh = blockIdx.x;
    for (int e = threadIdx.x; e < DK * DK; e += 256) {
        float s = 0.0f;
        #pragma unroll
        for (int c = 0; c < NCHUNK; c++)
            s += g_Mpart[((size_t)bh * NCHUNK + c) * DK * DK + e];
        g_M[(size_t)bh * DK * DK + e] = s * SCALE;
    }
}

__global__ __launch_bounds__(256) void qm_kernel()
{
    const int h  = blockIdx.y;
    const int n0 = blockIdx.x * 32;
    const int b  = n0 / SEQ;
    const int bh = b * NHEAD + h;
    const int tid = threadIdx.x;

    __shared__ float Ms[DK * DK];
    __shared__ float Qs[32 * DK];

    const float4* msrc = (const float4*)(g_M + (size_t)bh * DK * DK);
    float4* mdst = (float4*)Ms;
    #pragma unroll
    for (int i = tid; i < 1024; i += 256) mdst[i] = msrc[i];

    for (int i = tid; i < 512; i += 256) {
        const int r = i >> 4;
        const int c = (i & 15) * 4;
        *(float4*)&Qs[r * 64 + c] =
            *(const float4*)(g_Qp + (size_t)(n0 + r) * D_MODEL + h * DK + c);
    }
    __syncthreads();

    const int r  = tid >> 3;
    const int j0 = (tid & 7) * 8;
    float acc[8];
    #pragma unroll
    for (int j = 0; j < 8; j++) acc[j] = 0.0f;

    #pragma unroll 8
    for (int i = 0; i < 64; i++) {
        const float qv = Qs[r * 64 + i];
        #pragma unroll
        for (int j = 0; j < 8; j++) acc[j] += qv * Ms[i * 64 + j0 + j];
    }

    float* xr = g_X + (size_t)(n0 + r) * D_MODEL + h * DK + j0;
    #pragma unroll
    for (int j = 0; j < 8; j++) xr[j] = acc[j];
}

__global__ __launch_bounds__(256) void mask_correction_kernel(const int* __restrict__ mask)
{
    const int s = blockIdx.x;
    const int* mrow = mask + (size_t)s * SEQ;
    for (int t = threadIdx.x; t < SEQ; t += 256) {
        if (mrow[t] == 0) {
            for (int b = 0; b < BATCH; b++) {
                const float* qrow = g_Qp + (size_t)(b * SEQ + s) * D_MODEL;
                const float* krow = g_Kp + (size_t)(b * SEQ + t) * D_MODEL;
                const float* vrow = g_Vp + (size_t)(b * SEQ + t) * D_MODEL;
                float* xrow = g_X + (size_t)(b * SEQ + s) * D_MODEL;
                for (int h = 0; h < NHEAD; h++) {
                    float raw = 0.0f;
                    #pragma unroll 8
                    for (int i = 0; i < DK; i++)
                        raw += qrow[h * DK + i] * krow[h * DK + i];
                    const float delta = NEGV - raw * SCALE;
                    for (int j = 0; j < DK; j++)
                        atomicAdd(&xrow[h * DK + j], delta * vrow[h * DK + j]);
                }
            }
        }
    }
}

// ---------------------------------------------------------------------------
extern "C" void kernel_launch(void* const* d_in, const int* in_sizes, int n_in,
                              void* d_out, int out_size)
{
    const float* q    = (const float*)d_in[0];
    const float* k    = (const float*)d_in[1];
    const float* v    = (const float*)d_in[2];
    const int*   mask = (const int*)  d_in[3];
    const float* w_q  = (const float*)d_in[4];
    const float* b_q  = (const float*)d_in[5];
    const float* w_k  = (const float*)d_in[6];
    const float* b_k  = (const float*)d_in[7];
    const float* w_v  = (const float*)d_in[8];
    const float* b_v  = (const float*)d_in[9];
    const float* w_o  = (const float*)d_in[10];
    const float* b_o  = (const float*)d_in[11];
    float* out = (float*)d_out;

    float *Qp = nullptr, *Kp = nullptr, *Vp = nullptr, *X = nullptr;
    __nv_bfloat16 *Aext = nullptr, *Wext = nullptr;
    cudaGetSymbolAddress((void**)&Qp,   g_Qp);
    cudaGetSymbolAddress((void**)&Kp,   g_Kp);
    cudaGetSymbolAddress((void**)&Vp,   g_Vp);
    cudaGetSymbolAddress((void**)&X,    g_X);
    cudaGetSymbolAddress((void**)&Aext, g_Aext);
    cudaGetSymbolAddress((void**)&Wext, g_Wext);

    const int actTotal = NTOK * D_MODEL;
    const dim3 cwg(D_MODEL / 32, D_MODEL / 32);       // (24,24)
    const dim3 gg(D_MODEL / 64, NTOK / 128);           // (12, 32)
    const int actBlocks = (actTotal + 255) / 256;

    convert_w<<<cwg, 256>>>(w_q, Wext);
    convert_act<<<actBlocks, 256>>>(q, Aext, actTotal);
    gemm_hmma<<<gg, 256>>>(Aext, Wext, b_q, Qp);

    convert_w<<<cwg, 256>>>(w_k, Wext);
    convert_act<<<actBlocks, 256>>>(k, Aext, actTotal);
    gemm_hmma<<<gg, 256>>>(Aext, Wext, b_k, Kp);

    convert_w<<<cwg, 256>>>(w_v, Wext);
    convert_act<<<actBlocks, 256>>>(v, Aext, actTotal);
    gemm_hmma<<<gg, 256>>>(Aext, Wext, b_v, Vp);

    kv_partial_kernel<<<dim3(NCHUNK, BHTOT), 256>>>();
    kv_reduce_kernel<<<BHTOT, 256>>>();
    qm_kernel<<<dim3(NTOK / 32, NHEAD), 256>>>();
    mask_correction_kernel<<<SEQ, 256>>>(mask);

    convert_w<<<cwg, 256>>>(w_o, Wext);
    convert_act<<<actBlocks, 256>>>(X, Aext, actTotal);
    gemm_hmma<<<gg, 256>>>(Aext, Wext, b_o, out);
}